// round 2
// baseline (speedup 1.0000x reference)
#include <cuda_runtime.h>
#include <math.h>

// Problem constants
#define B_  2
#define S_  2048
#define D_  1024
#define H_  16
#define DH_ 64
#define M_  (B_ * S_)   // 4096 rows for all projection GEMMs

// Scratch (allocation-free rule: __device__ globals)
__device__ float g_q[M_ * D_];
__device__ float g_k[M_ * D_];
__device__ float g_v[M_ * D_];
__device__ float g_attn[M_ * D_];

// ---------------------------------------------------------------------------
// GEMM: C[M,N] = A[M,K] * W[K,N] + bias[N]
// 64x64 block tile, 256 threads, 4x4 per-thread microtile, BK=16.
// Thread (ty,tx): rows 4*ty+i, cols 4*tx+j.
// ---------------------------------------------------------------------------
__global__ __launch_bounds__(256) void gemm_bias_kernel(
    const float* __restrict__ A, const float* __restrict__ W,
    const float* __restrict__ bias, float* __restrict__ C,
    int M, int N, int K)
{
    __shared__ float As[64][16];   // [m][k], reads are row-broadcast -> no pad needed
    __shared__ float Ws[16][64];   // [k][n], reads contiguous over n -> no pad needed

    const int tid = threadIdx.x;
    const int tx = tid & 15;
    const int ty = tid >> 4;
    const int row0 = blockIdx.x * 64;
    const int col0 = blockIdx.y * 64;

    float acc[4][4] = {};

    for (int k0 = 0; k0 < K; k0 += 16) {
        // Load A tile: 64x16 floats, 1 float4 per thread (sequential smem stores)
        {
            int r  = tid >> 2;          // 0..63
            int c4 = (tid & 3) << 2;    // 0,4,8,12
            *(float4*)&As[r][c4] =
                *(const float4*)&A[(size_t)(row0 + r) * K + k0 + c4];
            // Load W tile: 16x64 floats, 1 float4 per thread
            int wr = tid >> 4;          // 0..15
            int wc = (tid & 15) << 2;   // 0..60
            *(float4*)&Ws[wr][wc] =
                *(const float4*)&W[(size_t)(k0 + wr) * N + col0 + wc];
        }
        __syncthreads();

#pragma unroll
        for (int kk = 0; kk < 16; kk += 4) {
            float a_[4][4];  // a_[i][kc]
            float b_[4][4];  // b_[kc][j]
#pragma unroll
            for (int i = 0; i < 4; i++)
                *(float4*)a_[i] = *(const float4*)&As[4 * ty + i][kk];
#pragma unroll
            for (int kc = 0; kc < 4; kc++)
                *(float4*)b_[kc] = *(const float4*)&Ws[kk + kc][4 * tx];
#pragma unroll
            for (int i = 0; i < 4; i++)
#pragma unroll
                for (int kc = 0; kc < 4; kc++)
#pragma unroll
                    for (int j = 0; j < 4; j++)
                        acc[i][j] += a_[i][kc] * b_[kc][j];
        }
        __syncthreads();
    }

    // Epilogue: bias add + float4 stores
    float4 bv = *(const float4*)&bias[col0 + 4 * tx];
#pragma unroll
    for (int i = 0; i < 4; i++) {
        float4 o;
        o.x = acc[i][0] + bv.x;
        o.y = acc[i][1] + bv.y;
        o.z = acc[i][2] + bv.z;
        o.w = acc[i][3] + bv.w;
        *(float4*)&C[(size_t)(row0 + 4 * ty + i) * N + col0 + 4 * tx] = o;
    }
}

// ---------------------------------------------------------------------------
// Flash attention (fp32, online softmax).
// Grid: (S/64, H, B). Block: 256 threads (16x16).
// Tiles: BQ=64 q-rows, BKV=64 keys, DH=64.
// Thread (ty,tx): score rows r_i = 4*ty+i, score cols c_j = tx+16*j.
//   -> K-tile float4 reads at pitch 68 floats are conflict-free
//      (lane byte stride 272 mod 128 = 16).
// Q/K/V layout in global: [B*S, D] with head offset h*64 (row stride D=1024).
// ---------------------------------------------------------------------------
#define KSTR 68   // padded row pitch (floats) for K and P tiles

__global__ __launch_bounds__(256) void flash_attn_kernel(
    const float* __restrict__ Q, const float* __restrict__ Kg,
    const float* __restrict__ Vg, float* __restrict__ Og)
{
    extern __shared__ float sm[];
    float* Qs = sm;                    // 64 * 64
    float* Ks = Qs + 64 * 64;          // 64 * KSTR
    float* Vs = Ks + 64 * KSTR;        // 64 * 64
    float* Ps = Vs + 64 * 64;          // 64 * KSTR

    const int tid = threadIdx.x;
    const int tx = tid & 15;
    const int ty = tid >> 4;
    const int q0 = blockIdx.x * 64;
    const int h  = blockIdx.y;
    const int b  = blockIdx.z;

    const size_t base = (size_t)b * S_ * D_ + (size_t)h * DH_;
    const float* Qp = Q + base + (size_t)q0 * D_;

    // Load Q tile once: 64 rows x 64 d, 4 float4 per thread, sequential stores
    {
        int r  = tid >> 2;           // 0..63
        int cg = (tid & 3) << 4;     // 0,16,32,48
#pragma unroll
        for (int u = 0; u < 4; u++)
            *(float4*)&Qs[r * 64 + cg + 4 * u] =
                *(const float4*)&Qp[(size_t)r * D_ + cg + 4 * u];
    }

    float m[4], l[4], o[4][4];
#pragma unroll
    for (int i = 0; i < 4; i++) {
        m[i] = -1e30f;
        l[i] = 0.f;
#pragma unroll
        for (int j = 0; j < 4; j++) o[i][j] = 0.f;
    }
    const float scale = 0.125f;  // 1/sqrt(64)

    for (int kt = 0; kt < S_; kt += 64) {
        const float* Kp = Kg + base + (size_t)kt * D_;
        const float* Vp = Vg + base + (size_t)kt * D_;

        __syncthreads();   // previous iter's Ps/Vs reads done before overwrite
        {
            int r  = tid >> 2;
            int cg = (tid & 3) << 4;
#pragma unroll
            for (int u = 0; u < 4; u++) {
                *(float4*)&Ks[r * KSTR + cg + 4 * u] =
                    *(const float4*)&Kp[(size_t)r * D_ + cg + 4 * u];
                *(float4*)&Vs[r * 64 + cg + 4 * u] =
                    *(const float4*)&Vp[(size_t)r * D_ + cg + 4 * u];
            }
        }
        __syncthreads();

        // S = Q * K^T  (vectorized over d)
        float s[4][4] = {};
#pragma unroll 4
        for (int d4 = 0; d4 < 64; d4 += 4) {
            float qv[4][4], kv[4][4];
#pragma unroll
            for (int i = 0; i < 4; i++)
                *(float4*)qv[i] = *(const float4*)&Qs[(4 * ty + i) * 64 + d4];
#pragma unroll
            for (int j = 0; j < 4; j++)
                *(float4*)kv[j] = *(const float4*)&Ks[(tx + 16 * j) * KSTR + d4];
#pragma unroll
            for (int i = 0; i < 4; i++)
#pragma unroll
                for (int j = 0; j < 4; j++)
#pragma unroll
                    for (int d = 0; d < 4; d++)
                        s[i][j] += qv[i][d] * kv[j][d];
        }

        // Online softmax update + store P
#pragma unroll
        for (int i = 0; i < 4; i++) {
            float rmax = -1e30f;
#pragma unroll
            for (int j = 0; j < 4; j++) {
                s[i][j] *= scale;
                rmax = fmaxf(rmax, s[i][j]);
            }
#pragma unroll
            for (int off = 8; off; off >>= 1)
                rmax = fmaxf(rmax, __shfl_xor_sync(0xffffffffu, rmax, off));
            float mn = fmaxf(m[i], rmax);
            float f  = __expf(m[i] - mn);
            float rsum = 0.f;
#pragma unroll
            for (int j = 0; j < 4; j++) {
                s[i][j] = __expf(s[i][j] - mn);
                rsum += s[i][j];
            }
#pragma unroll
            for (int off = 8; off; off >>= 1)
                rsum += __shfl_xor_sync(0xffffffffu, rsum, off);
            l[i] = l[i] * f + rsum;
            m[i] = mn;
#pragma unroll
            for (int j = 0; j < 4; j++) {
                o[i][j] *= f;
                Ps[(4 * ty + i) * KSTR + tx + 16 * j] = s[i][j];
            }
        }
        __syncthreads();

        // O += P * V   (vectorized over c for P, scalar conflict-free V reads)
#pragma unroll 4
        for (int c4 = 0; c4 < 64; c4 += 4) {
            float pv[4][4], vv[4][4];
#pragma unroll
            for (int i = 0; i < 4; i++)
                *(float4*)pv[i] = *(const float4*)&Ps[(4 * ty + i) * KSTR + c4];
#pragma unroll
            for (int cc = 0; cc < 4; cc++)
#pragma unroll
                for (int j = 0; j < 4; j++)
                    vv[cc][j] = Vs[(c4 + cc) * 64 + tx + 16 * j];
#pragma unroll
            for (int i = 0; i < 4; i++)
#pragma unroll
                for (int cc = 0; cc < 4; cc++)
#pragma unroll
                    for (int j = 0; j < 4; j++)
                        o[i][j] += pv[i][cc] * vv[cc][j];
        }
    }

    // Normalize + write out in [B*S, D] layout (head-interleaved, D contiguous)
#pragma unroll
    for (int i = 0; i < 4; i++) {
        float inv = 1.f / l[i];
#pragma unroll
        for (int j = 0; j < 4; j++)
            Og[base + (size_t)(q0 + 4 * ty + i) * D_ + tx + 16 * j] = o[i][j] * inv;
    }
}

// ---------------------------------------------------------------------------
// Launch: 3 projection GEMMs -> flash attention -> output GEMM.
// All on default stream (sequential deps). Graph-capturable, no allocs.
// ---------------------------------------------------------------------------
extern "C" void kernel_launch(void* const* d_in, const int* in_sizes, int n_in,
                              void* d_out, int out_size)
{
    const float* x  = (const float*)d_in[0];
    const float* Wq = (const float*)d_in[1];
    const float* bq = (const float*)d_in[2];
    const float* Wk = (const float*)d_in[3];
    const float* bk = (const float*)d_in[4];
    const float* Wv = (const float*)d_in[5];
    const float* bv = (const float*)d_in[6];
    const float* Wo = (const float*)d_in[7];
    const float* bo = (const float*)d_in[8];
    float* out = (float*)d_out;

    float *qp, *kp, *vp, *ap;
    cudaGetSymbolAddress((void**)&qp, g_q);
    cudaGetSymbolAddress((void**)&kp, g_k);
    cudaGetSymbolAddress((void**)&vp, g_v);
    cudaGetSymbolAddress((void**)&ap, g_attn);

    dim3 gemm_grid(M_ / 64, D_ / 64);   // (64, 16)
    dim3 blk(256);

    gemm_bias_kernel<<<gemm_grid, blk>>>(x, Wq, bq, qp, M_, D_, D_);
    gemm_bias_kernel<<<gemm_grid, blk>>>(x, Wk, bk, kp, M_, D_, D_);
    gemm_bias_kernel<<<gemm_grid, blk>>>(x, Wv, bv, vp, M_, D_, D_);

    int attn_smem = (64 * 64 + 64 * KSTR + 64 * 64 + 64 * KSTR) * (int)sizeof(float);
    cudaFuncSetAttribute(flash_attn_kernel,
                         cudaFuncAttributeMaxDynamicSharedMemorySize, attn_smem);
    flash_attn_kernel<<<dim3(S_ / 64, H_, B_), blk, attn_smem>>>(qp, kp, vp, ap);

    gemm_bias_kernel<<<gemm_grid, blk>>>(ap, Wo, bo, out, M_, D_, D_);
}